// round 3
// baseline (speedup 1.0000x reference)
#include <cuda_runtime.h>
#include <cuda_bf16.h>
#include <cstdint>

// out[m,n] = sum_k X[m,k]*W[n,k] + sum_r T[m,r]*A[n,r],  T = X @ B^T
// X:[256,8192] W:[8192,8192] A:[8192,16] B:[16,8192] f32. ALPHA=BETA=1.
// NOTE: harness PTX target is sm_103 (no 'a') -> tcgen05 unavailable.
// This uses the legacy mma.sync.m16n8k8.tf32 path, tuned for latency hiding.

#define M_TOT 256
#define N_TOT 8192
#define K_TOT 8192
#define R_LORA 16

#define BN 64
#define BK 32
#define NT (K_TOT / BK)       // 256
#define NSTG 4
#define XS_STRIDE 36          // 32 + 4 pad floats: conflict-free fragment LDS
#define X_STG (M_TOT * XS_STRIDE)          // floats per X stage (9216)
#define W_STG (BN * XS_STRIDE)             // floats per W stage (2304)
#define STG_FLOATS (X_STG + W_STG)         // 11520
#define TS_STRIDE 17
#define AS_STRIDE 17
#define SMEM_FLOATS (NSTG * STG_FLOATS + M_TOT * TS_STRIDE + BN * AS_STRIDE)
#define SMEM_BYTES (SMEM_FLOATS * 4)       // 46080*4 + 17408 + 4352 = 206080

__device__ float g_T[M_TOT * R_LORA];

// ---------------------------------------------------------------------------
__device__ __forceinline__ unsigned f2tf32(float f) {
    unsigned u;
    asm("cvt.rna.tf32.f32 %0, %1;\n" : "=r"(u) : "f"(f));   // NOT volatile
    return u;
}
__device__ __forceinline__ void cp_async16(void* smem_dst, const void* gmem_src) {
    unsigned s = (unsigned)__cvta_generic_to_shared(smem_dst);
    asm volatile("cp.async.cg.shared.global [%0], [%1], 16;\n" :: "r"(s), "l"(gmem_src));
}
__device__ __forceinline__ void cp_commit() {
    asm volatile("cp.async.commit_group;\n");
}
template <int N>
__device__ __forceinline__ void cp_wait() {
    asm volatile("cp.async.wait_group %0;\n" :: "n"(N));
}
__device__ __forceinline__ void mma_tf32(float c[4], const unsigned a[4], const unsigned b[2]) {
    asm("mma.sync.aligned.m16n8k8.row.col.f32.tf32.tf32.f32 "
        "{%0,%1,%2,%3}, {%4,%5,%6,%7}, {%8,%9}, {%0,%1,%2,%3};\n"
        : "+f"(c[0]), "+f"(c[1]), "+f"(c[2]), "+f"(c[3])
        : "r"(a[0]), "r"(a[1]), "r"(a[2]), "r"(a[3]), "r"(b[0]), "r"(b[1]));
}

// ---------------------------------------------------------------------------
// Kernel 1: T[m,r] = sum_k X[m,k] * B[r,k]   (exact fp32, proven)
// ---------------------------------------------------------------------------
__global__ __launch_bounds__(256, 1) void lora_xbt_kernel(
    const float* __restrict__ X, const float* __restrict__ Bm)
{
    __shared__ float red[8][64];
    const int tid = threadIdx.x;
    const int m0 = blockIdx.x * 4;

    float acc[4][16];
#pragma unroll
    for (int mm = 0; mm < 4; mm++)
#pragma unroll
        for (int r = 0; r < 16; r++) acc[mm][r] = 0.f;

    for (int k0 = tid * 4; k0 < K_TOT; k0 += 256 * 4) {
        float4 xv[4];
#pragma unroll
        for (int mm = 0; mm < 4; mm++)
            xv[mm] = *reinterpret_cast<const float4*>(X + (size_t)(m0 + mm) * K_TOT + k0);
#pragma unroll
        for (int r = 0; r < 16; r++) {
            float4 bv = *reinterpret_cast<const float4*>(Bm + (size_t)r * K_TOT + k0);
#pragma unroll
            for (int mm = 0; mm < 4; mm++)
                acc[mm][r] += xv[mm].x * bv.x + xv[mm].y * bv.y +
                              xv[mm].z * bv.z + xv[mm].w * bv.w;
        }
    }
#pragma unroll
    for (int mm = 0; mm < 4; mm++)
#pragma unroll
        for (int r = 0; r < 16; r++) {
            float v = acc[mm][r];
#pragma unroll
            for (int o = 16; o > 0; o >>= 1) v += __shfl_xor_sync(0xffffffffu, v, o);
            if ((tid & 31) == 0) red[tid >> 5][mm * 16 + r] = v;
        }
    __syncthreads();
    if (tid < 64) {
        float s = 0.f;
#pragma unroll
        for (int w = 0; w < 8; w++) s += red[w][tid];
        g_T[(size_t)(m0 + (tid >> 4)) * 16 + (tid & 15)] = s;
    }
}

// ---------------------------------------------------------------------------
// Kernel 2: GEMM + LoRA epilogue.
// CTA: 256(M) x 64(N), grid 128 (W streamed from HBM exactly once).
// 512 threads = 16 warps in 8(M) x 2(N); warp tile 32x32 (mi=2, ni=4).
// 4-stage cp.async pipeline over BK=32.
// ---------------------------------------------------------------------------
__global__ __launch_bounds__(512, 1) void lora_gemm_kernel(
    const float* __restrict__ X, const float* __restrict__ W,
    const float* __restrict__ A, float* __restrict__ Out)
{
    extern __shared__ float smem[];
    float* Ts = smem + NSTG * STG_FLOATS;              // 256 x 17
    float* As = Ts + M_TOT * TS_STRIDE;                // 64 x 17

    const int tid = threadIdx.x;
    const int n0 = blockIdx.x * BN;
    const int warp = tid >> 5;
    const int lane = tid & 31;
    const int g = lane >> 2;          // 0..7
    const int tig = lane & 3;         // 0..3
    const int mbase = (warp >> 1) * 32;   // 0,32,...,224
    const int nbase = (warp & 1) * 32;    // 0 or 32

    // loader mapping: X tile 256x32 floats = 2048 float4 (4 per thread),
    //                 W tile 64x32 floats = 512 float4 (1 per thread)
    const int xr0 = tid >> 3;             // base row for X (0..63), +64 strides
    const int c4 = (tid & 7) * 4;         // float col within tile
    const int wr = tid >> 3;              // W row 0..63
    const bool w_active = tid < 512;      // always true; W uses all 512? 64*8=512 ✓

    // stage LoRA operands (stride 17 kills epilogue bank conflicts)
    for (int i = tid; i < M_TOT * R_LORA; i += 512)
        Ts[(i >> 4) * TS_STRIDE + (i & 15)] = g_T[i];
    for (int i = tid; i < BN * R_LORA; i += 512)
        As[(i >> 4) * AS_STRIDE + (i & 15)] = A[(size_t)n0 * R_LORA + i];

    float c[2][4][4];
#pragma unroll
    for (int mi = 0; mi < 2; mi++)
#pragma unroll
        for (int ni = 0; ni < 4; ni++)
#pragma unroll
            for (int q = 0; q < 4; q++) c[mi][ni][q] = 0.f;

    // prologue: load tiles 0,1,2
#pragma unroll
    for (int t = 0; t < NSTG - 1; t++) {
        float* xd = smem + t * STG_FLOATS;
        float* wd = xd + X_STG;
        const int kt = t * BK;
#pragma unroll
        for (int i = 0; i < 4; i++) {
            int row = xr0 + 64 * i;
            cp_async16(&xd[row * XS_STRIDE + c4], X + (size_t)row * K_TOT + kt + c4);
        }
        cp_async16(&wd[wr * XS_STRIDE + c4], W + (size_t)(n0 + wr) * K_TOT + kt + c4);
        cp_commit();
    }

    for (int t = 0; t < NT; t++) {
        __syncthreads();   // all warps done with buffer (t-1)%4 before overwrite
        if (t + NSTG - 1 < NT) {
            const int tn = t + NSTG - 1;
            float* xd = smem + (tn & (NSTG - 1)) * STG_FLOATS;
            float* wd = xd + X_STG;
            const int kt = tn * BK;
#pragma unroll
            for (int i = 0; i < 4; i++) {
                int row = xr0 + 64 * i;
                cp_async16(&xd[row * XS_STRIDE + c4], X + (size_t)row * K_TOT + kt + c4);
            }
            cp_async16(&wd[wr * XS_STRIDE + c4], W + (size_t)(n0 + wr) * K_TOT + kt + c4);
        }
        cp_commit();
        cp_wait<NSTG - 1>();   // tile t resident
        __syncthreads();

        const float* xb = smem + (t & (NSTG - 1)) * STG_FLOATS;
        const float* wb = xb + X_STG;

#pragma unroll
        for (int kk = 0; kk < BK / 8; kk++) {
            const int k = kk * 8;
            unsigned af[2][4], bf[4][2];
#pragma unroll
            for (int mi = 0; mi < 2; mi++) {
                const float* xr = xb + (mbase + mi * 16 + g) * XS_STRIDE + k + tig;
                af[mi][0] = f2tf32(xr[0]);
                af[mi][1] = f2tf32(xr[8 * XS_STRIDE]);
                af[mi][2] = f2tf32(xr[4]);
                af[mi][3] = f2tf32(xr[8 * XS_STRIDE + 4]);
            }
#pragma unroll
            for (int ni = 0; ni < 4; ni++) {
                const float* wrp = wb + (nbase + ni * 8 + g) * XS_STRIDE + k + tig;
                bf[ni][0] = f2tf32(wrp[0]);
                bf[ni][1] = f2tf32(wrp[4]);
            }
#pragma unroll
            for (int mi = 0; mi < 2; mi++)
#pragma unroll
                for (int ni = 0; ni < 4; ni++)
                    mma_tf32(c[mi][ni], af[mi], bf[ni]);
        }
    }
    __syncthreads();

    // epilogue: exact fp32 rank-16 LoRA correction + direct stores
#pragma unroll
    for (int mi = 0; mi < 2; mi++) {
        const int m0r = mbase + mi * 16 + g;
        const int m1r = m0r + 8;
#pragma unroll
        for (int ni = 0; ni < 4; ni++) {
            const int nl = nbase + ni * 8 + 2 * tig;
            float d00 = 0.f, d01 = 0.f, d10 = 0.f, d11 = 0.f;
#pragma unroll
            for (int r = 0; r < R_LORA; r++) {
                float t0 = Ts[m0r * TS_STRIDE + r];
                float t1 = Ts[m1r * TS_STRIDE + r];
                float a0 = As[nl * AS_STRIDE + r];
                float a1 = As[(nl + 1) * AS_STRIDE + r];
                d00 += t0 * a0;
                d01 += t0 * a1;
                d10 += t1 * a0;
                d11 += t1 * a1;
            }
            size_t o0 = (size_t)m0r * N_TOT + n0 + nl;
            size_t o1 = (size_t)m1r * N_TOT + n0 + nl;
            float2 v0 = make_float2(c[mi][ni][0] + d00, c[mi][ni][1] + d01);
            float2 v1 = make_float2(c[mi][ni][2] + d10, c[mi][ni][3] + d11);
            *reinterpret_cast<float2*>(Out + o0) = v0;
            *reinterpret_cast<float2*>(Out + o1) = v1;
        }
    }
}

// ---------------------------------------------------------------------------
extern "C" void kernel_launch(void* const* d_in, const int* in_sizes, int n_in,
                              void* d_out, int out_size)
{
    const float* x  = (const float*)d_in[0];  // [4,64,8192]
    const float* W  = (const float*)d_in[1];  // [8192,8192]
    const float* A  = (const float*)d_in[2];  // [8192,16]
    const float* Bm = (const float*)d_in[3];  // [16,8192]
    float* out = (float*)d_out;               // [4,64,8192]

    cudaFuncSetAttribute(lora_gemm_kernel,
                         cudaFuncAttributeMaxDynamicSharedMemorySize, SMEM_BYTES);

    lora_xbt_kernel<<<64, 256>>>(x, Bm);
    lora_gemm_kernel<<<N_TOT / BN, 512, SMEM_BYTES>>>(x, W, A, out);
}

// round 4
// speedup vs baseline: 1.1791x; 1.1791x over previous
#include <cuda_runtime.h>
#include <cuda_bf16.h>
#include <cstdint>

// out[m,n] = sum_k X[m,k]*W[n,k] + sum_r T[m,r]*A[n,r],  T = X @ B^T
// X:[256,8192] W:[8192,8192] A:[8192,16] B:[16,8192] f32. ALPHA=BETA=1.
// mma.sync.m16n8k8.tf32 path (sm_103 PTX target: no tcgen05).
// f32 bits fed directly to tf32 mma (HW truncates) -> no cvt on ALU pipe.

#define M_TOT 256
#define N_TOT 8192
#define K_TOT 8192
#define R_LORA 16

#define BN 64
#define BK 32
#define NT (K_TOT / BK)       // 256
#define NSTG 4
#define XS_STRIDE 36          // 32 + 4 pad floats: conflict-free fragment LDS
#define X_STG (M_TOT * XS_STRIDE)          // 9216 floats
#define W_STG (BN * XS_STRIDE)             // 2304 floats
#define STG_FLOATS (X_STG + W_STG)         // 11520
#define TS_STRIDE 17
#define AS_STRIDE 17
#define SMEM_FLOATS (NSTG * STG_FLOATS + M_TOT * TS_STRIDE + BN * AS_STRIDE)
#define SMEM_BYTES (SMEM_FLOATS * 4)

__device__ float g_T[M_TOT * R_LORA];

// ---------------------------------------------------------------------------
__device__ __forceinline__ void cp_async16(void* smem_dst, const void* gmem_src) {
    unsigned s = (unsigned)__cvta_generic_to_shared(smem_dst);
    asm volatile("cp.async.cg.shared.global [%0], [%1], 16;\n" :: "r"(s), "l"(gmem_src));
}
__device__ __forceinline__ void cp_commit() {
    asm volatile("cp.async.commit_group;\n");
}
template <int N>
__device__ __forceinline__ void cp_wait() {
    asm volatile("cp.async.wait_group %0;\n" :: "n"(N));
}
__device__ __forceinline__ void mma_tf32(float c[4], const unsigned a[4], const unsigned b[2]) {
    asm("mma.sync.aligned.m16n8k8.row.col.f32.tf32.tf32.f32 "
        "{%0,%1,%2,%3}, {%4,%5,%6,%7}, {%8,%9}, {%0,%1,%2,%3};\n"
        : "+f"(c[0]), "+f"(c[1]), "+f"(c[2]), "+f"(c[3])
        : "r"(a[0]), "r"(a[1]), "r"(a[2]), "r"(a[3]), "r"(b[0]), "r"(b[1]));
}

// ---------------------------------------------------------------------------
// Kernel 1: T[m,r] = sum_k X[m,k] * B[r,k]   (exact fp32, proven)
// ---------------------------------------------------------------------------
__global__ __launch_bounds__(256, 1) void lora_xbt_kernel(
    const float* __restrict__ X, const float* __restrict__ Bm)
{
    __shared__ float red[8][64];
    const int tid = threadIdx.x;
    const int m0 = blockIdx.x * 4;

    float acc[4][16];
#pragma unroll
    for (int mm = 0; mm < 4; mm++)
#pragma unroll
        for (int r = 0; r < 16; r++) acc[mm][r] = 0.f;

    for (int k0 = tid * 4; k0 < K_TOT; k0 += 256 * 4) {
        float4 xv[4];
#pragma unroll
        for (int mm = 0; mm < 4; mm++)
            xv[mm] = *reinterpret_cast<const float4*>(X + (size_t)(m0 + mm) * K_TOT + k0);
#pragma unroll
        for (int r = 0; r < 16; r++) {
            float4 bv = *reinterpret_cast<const float4*>(Bm + (size_t)r * K_TOT + k0);
#pragma unroll
            for (int mm = 0; mm < 4; mm++)
                acc[mm][r] += xv[mm].x * bv.x + xv[mm].y * bv.y +
                              xv[mm].z * bv.z + xv[mm].w * bv.w;
        }
    }
#pragma unroll
    for (int mm = 0; mm < 4; mm++)
#pragma unroll
        for (int r = 0; r < 16; r++) {
            float v = acc[mm][r];
#pragma unroll
            for (int o = 16; o > 0; o >>= 1) v += __shfl_xor_sync(0xffffffffu, v, o);
            if ((tid & 31) == 0) red[tid >> 5][mm * 16 + r] = v;
        }
    __syncthreads();
    if (tid < 64) {
        float s = 0.f;
#pragma unroll
        for (int w = 0; w < 8; w++) s += red[w][tid];
        g_T[(size_t)(m0 + (tid >> 4)) * 16 + (tid & 15)] = s;
    }
}

// ---------------------------------------------------------------------------
// Kernel 2: GEMM + LoRA epilogue.
// CTA: 256(M) x 64(N), grid 128 (W streamed from HBM exactly once).
// 512 threads = 16 warps in 8(M) x 2(N); warp tile 32x32.
// 4-stage cp.async pipeline, ONE barrier per tile.
// ---------------------------------------------------------------------------
__global__ __launch_bounds__(512, 1) void lora_gemm_kernel(
    const float* __restrict__ X, const float* __restrict__ W,
    const float* __restrict__ A, float* __restrict__ Out)
{
    extern __shared__ float smem[];
    float* Ts = smem + NSTG * STG_FLOATS;              // 256 x 17
    float* As = Ts + M_TOT * TS_STRIDE;                // 64 x 17

    const int tid = threadIdx.x;
    const int n0 = blockIdx.x * BN;
    const int warp = tid >> 5;
    const int lane = tid & 31;
    const int g = lane >> 2;          // 0..7
    const int tig = lane & 3;         // 0..3
    const int mbase = (warp >> 1) * 32;   // 0,32,...,224
    const int nbase = (warp & 1) * 32;    // 0 or 32

    const int xr0 = tid >> 3;             // X rows xr0, +64, +128, +192
    const int c4 = (tid & 7) * 4;         // float col within tile
    const int wr = tid >> 3;              // W row 0..63

    // stage LoRA operands (stride 17: no epilogue bank conflicts)
    for (int i = tid; i < M_TOT * R_LORA; i += 512)
        Ts[(i >> 4) * TS_STRIDE + (i & 15)] = g_T[i];
    for (int i = tid; i < BN * R_LORA; i += 512)
        As[(i >> 4) * AS_STRIDE + (i & 15)] = A[(size_t)n0 * R_LORA + i];

    float c[2][4][4];
#pragma unroll
    for (int mi = 0; mi < 2; mi++)
#pragma unroll
        for (int ni = 0; ni < 4; ni++)
#pragma unroll
            for (int q = 0; q < 4; q++) c[mi][ni][q] = 0.f;

    // prologue: issue tiles 0,1,2
#pragma unroll
    for (int t = 0; t < NSTG - 1; t++) {
        float* xd = smem + t * STG_FLOATS;
        float* wd = xd + X_STG;
        const int kt = t * BK;
#pragma unroll
        for (int i = 0; i < 4; i++) {
            int row = xr0 + 64 * i;
            cp_async16(&xd[row * XS_STRIDE + c4], X + (size_t)row * K_TOT + kt + c4);
        }
        cp_async16(&wd[wr * XS_STRIDE + c4], W + (size_t)(n0 + wr) * K_TOT + kt + c4);
        cp_commit();
    }

    for (int t = 0; t < NT; t++) {
        cp_wait<NSTG - 2>();   // this thread's copies of tile t have landed
        __syncthreads();       // everyone's copies landed; all done computing t-1

        // issue loads for tile t+3 into buffer (t-1)&3 (free: compute t-1 done)
        if (t + NSTG - 1 < NT) {
            const int tn = t + NSTG - 1;
            float* xd = smem + (tn & (NSTG - 1)) * STG_FLOATS;
            float* wd = xd + X_STG;
            const int kt = tn * BK;
#pragma unroll
            for (int i = 0; i < 4; i++) {
                int row = xr0 + 64 * i;
                cp_async16(&xd[row * XS_STRIDE + c4], X + (size_t)row * K_TOT + kt + c4);
            }
            cp_async16(&wd[wr * XS_STRIDE + c4], W + (size_t)(n0 + wr) * K_TOT + kt + c4);
        }
        cp_commit();           // keep group count in lockstep on all threads

        const float* xb = smem + (t & (NSTG - 1)) * STG_FLOATS;
        const float* wb = xb + X_STG;

#pragma unroll
        for (int kk = 0; kk < BK / 8; kk++) {
            const int k = kk * 8;
            unsigned af[2][4], bf[4][2];
#pragma unroll
            for (int mi = 0; mi < 2; mi++) {
                const float* xr = xb + (mbase + mi * 16 + g) * XS_STRIDE + k + tig;
                af[mi][0] = __float_as_uint(xr[0]);
                af[mi][1] = __float_as_uint(xr[8 * XS_STRIDE]);
                af[mi][2] = __float_as_uint(xr[4]);
                af[mi][3] = __float_as_uint(xr[8 * XS_STRIDE + 4]);
            }
#pragma unroll
            for (int ni = 0; ni < 4; ni++) {
                const float* wrp = wb + (nbase + ni * 8 + g) * XS_STRIDE + k + tig;
                bf[ni][0] = __float_as_uint(wrp[0]);
                bf[ni][1] = __float_as_uint(wrp[4]);
            }
#pragma unroll
            for (int mi = 0; mi < 2; mi++)
#pragma unroll
                for (int ni = 0; ni < 4; ni++)
                    mma_tf32(c[mi][ni], af[mi], bf[ni]);
        }
    }
    __syncthreads();

    // epilogue: exact fp32 rank-16 LoRA correction + direct stores
#pragma unroll
    for (int mi = 0; mi < 2; mi++) {
        const int m0r = mbase + mi * 16 + g;
        const int m1r = m0r + 8;
#pragma unroll
        for (int ni = 0; ni < 4; ni++) {
            const int nl = nbase + ni * 8 + 2 * tig;
            float d00 = 0.f, d01 = 0.f, d10 = 0.f, d11 = 0.f;
#pragma unroll
            for (int r = 0; r < R_LORA; r++) {
                float t0 = Ts[m0r * TS_STRIDE + r];
                float t1 = Ts[m1r * TS_STRIDE + r];
                float a0 = As[nl * AS_STRIDE + r];
                float a1 = As[(nl + 1) * AS_STRIDE + r];
                d00 += t0 * a0;
                d01 += t0 * a1;
                d10 += t1 * a0;
                d11 += t1 * a1;
            }
            size_t o0 = (size_t)m0r * N_TOT + n0 + nl;
            size_t o1 = (size_t)m1r * N_TOT + n0 + nl;
            float2 v0 = make_float2(c[mi][ni][0] + d00, c[mi][ni][1] + d01);
            float2 v1 = make_float2(c[mi][ni][2] + d10, c[mi][ni][3] + d11);
            *reinterpret_cast<float2*>(Out + o0) = v0;
            *reinterpret_cast<float2*>(Out + o1) = v1;
        }
    }
}

// ---------------------------------------------------------------------------
extern "C" void kernel_launch(void* const* d_in, const int* in_sizes, int n_in,
                              void* d_out, int out_size)
{
    const float* x  = (const float*)d_in[0];  // [4,64,8192]
    const float* W  = (const float*)d_in[1];  // [8192,8192]
    const float* A  = (const float*)d_in[2];  // [8192,16]
    const float* Bm = (const float*)d_in[3];  // [16,8192]
    float* out = (float*)d_out;               // [4,64,8192]

    cudaFuncSetAttribute(lora_gemm_kernel,
                         cudaFuncAttributeMaxDynamicSharedMemorySize, SMEM_BYTES);

    lora_xbt_kernel<<<64, 256>>>(x, Bm);
    lora_gemm_kernel<<<N_TOT / BN, 512, SMEM_BYTES>>>(x, W, A, out);
}

// round 9
// speedup vs baseline: 1.2923x; 1.0960x over previous
#include <cuda_runtime.h>
#include <cuda_bf16.h>
#include <cstdint>

// out[m,n] = sum_k X[m,k]*W[n,k] + sum_r T[m,r]*A[n,r],  T = X @ B^T
// X:[256,8192] W:[8192,8192] A:[8192,16] B:[16,8192] f32. ALPHA=BETA=1.
// mma.sync.m16n8k8.tf32 (sm_103 PTX target: no tcgen05), raw f32 bits fed to
// tf32 mma (HW truncates; no cvt on ALU pipe).
// R9: CTA 128x128, 256 thr = 8 warps in 4(M) x 2(N), warp tile 32x64
//     (1.5 LDS/mma). R5/R6 crash root-caused: 8 warps cannot tile 2x2 of
//     64x64 — warps 4-7 indexed out of bounds. This layout is consistent.

#define M_TOT 256
#define N_TOT 8192
#define K_TOT 8192
#define R_LORA 16

#define BM 128
#define BN 128
#define BK 32
#define NT (K_TOT / BK)       // 256
#define NSTG 4
#define XS_STRIDE 36          // 32 + 4 pad floats: conflict-free fragment LDS
#define X_STG (BM * XS_STRIDE)             // 4608 floats
#define W_STG (BN * XS_STRIDE)             // 4608 floats
#define STG_FLOATS (X_STG + W_STG)         // 9216
#define TS_STRIDE 17
#define AS_STRIDE 17
#define SMEM_FLOATS (NSTG * STG_FLOATS + BM * TS_STRIDE + BN * AS_STRIDE)
#define SMEM_BYTES (SMEM_FLOATS * 4)       // 164864

__device__ float g_T[M_TOT * R_LORA];

// ---------------------------------------------------------------------------
__device__ __forceinline__ void cp_async16(void* smem_dst, const void* gmem_src) {
    unsigned s = (unsigned)__cvta_generic_to_shared(smem_dst);
    asm volatile("cp.async.cg.shared.global [%0], [%1], 16;\n"
                 :: "r"(s), "l"(gmem_src) : "memory");
}
__device__ __forceinline__ void cp_commit() {
    asm volatile("cp.async.commit_group;\n" ::: "memory");
}
template <int N>
__device__ __forceinline__ void cp_wait() {
    asm volatile("cp.async.wait_group %0;\n" :: "n"(N) : "memory");
}
__device__ __forceinline__ void mma_tf32(float c[4], const unsigned a[4], const unsigned b[2]) {
    asm("mma.sync.aligned.m16n8k8.row.col.f32.tf32.tf32.f32 "
        "{%0,%1,%2,%3}, {%4,%5,%6,%7}, {%8,%9}, {%0,%1,%2,%3};\n"
        : "+f"(c[0]), "+f"(c[1]), "+f"(c[2]), "+f"(c[3])
        : "r"(a[0]), "r"(a[1]), "r"(a[2]), "r"(a[3]), "r"(b[0]), "r"(b[1]));
}

// ---------------------------------------------------------------------------
// Kernel 1: T[m,r] = sum_k X[m,k] * B[r,k]   (exact fp32, proven)
// ---------------------------------------------------------------------------
__global__ __launch_bounds__(256, 1) void lora_xbt_kernel(
    const float* __restrict__ X, const float* __restrict__ Bm)
{
    __shared__ float red[8][64];
    const int tid = threadIdx.x;
    const int m0 = blockIdx.x * 4;

    float acc[4][16];
#pragma unroll
    for (int mm = 0; mm < 4; mm++)
#pragma unroll
        for (int r = 0; r < 16; r++) acc[mm][r] = 0.f;

    for (int k0 = tid * 4; k0 < K_TOT; k0 += 256 * 4) {
        float4 xv[4];
#pragma unroll
        for (int mm = 0; mm < 4; mm++)
            xv[mm] = *reinterpret_cast<const float4*>(X + (size_t)(m0 + mm) * K_TOT + k0);
#pragma unroll
        for (int r = 0; r < 16; r++) {
            float4 bv = *reinterpret_cast<const float4*>(Bm + (size_t)r * K_TOT + k0);
#pragma unroll
            for (int mm = 0; mm < 4; mm++)
                acc[mm][r] += xv[mm].x * bv.x + xv[mm].y * bv.y +
                              xv[mm].z * bv.z + xv[mm].w * bv.w;
        }
    }
#pragma unroll
    for (int mm = 0; mm < 4; mm++)
#pragma unroll
        for (int r = 0; r < 16; r++) {
            float v = acc[mm][r];
#pragma unroll
            for (int o = 16; o > 0; o >>= 1) v += __shfl_xor_sync(0xffffffffu, v, o);
            if ((tid & 31) == 0) red[tid >> 5][mm * 16 + r] = v;
        }
    __syncthreads();
    if (tid < 64) {
        float s = 0.f;
#pragma unroll
        for (int w = 0; w < 8; w++) s += red[w][tid];
        g_T[(size_t)(m0 + (tid >> 4)) * 16 + (tid & 15)] = s;
    }
}

// ---------------------------------------------------------------------------
// Kernel 2: GEMM + LoRA epilogue.
// Grid 128 (1D): n-tile = bid & 63, m-half = bid >> 6.
// 256 threads = 8 warps in 4(M) x 2(N); warp tile 32x64 (mi=2, ni=8).
// 4-stage cp.async pipeline, one barrier per tile.
// ---------------------------------------------------------------------------
__global__ __launch_bounds__(256, 1) void lora_gemm_kernel(
    const float* __restrict__ X, const float* __restrict__ W,
    const float* __restrict__ A, float* __restrict__ Out)
{
    extern __shared__ float smem[];
    float* Ts = smem + NSTG * STG_FLOATS;              // 128 x 17
    float* As = Ts + BM * TS_STRIDE;                   // 128 x 17

    const int tid = threadIdx.x;
    const int n0 = (blockIdx.x & 63) * BN;
    const int m0g = (blockIdx.x >> 6) * BM;
    const int warp = tid >> 5;            // 0..7
    const int lane = tid & 31;
    const int g = lane >> 2;              // 0..7
    const int tig = lane & 3;             // 0..3
    const int mbase = (warp >> 1) * 32;   // 0,32,64,96  (4 M-slots)
    const int nbase = (warp & 1) * 64;    // 0,64        (2 N-slots)

    // stage LoRA operands (stride 17: conflict-free epilogue reads)
    for (int i = tid; i < BM * R_LORA; i += 256)
        Ts[(i >> 4) * TS_STRIDE + (i & 15)] = g_T[m0g * R_LORA + i];
    for (int i = tid; i < BN * R_LORA; i += 256)
        As[(i >> 4) * AS_STRIDE + (i & 15)] = A[(size_t)n0 * R_LORA + i];

    float c[2][8][4];
#pragma unroll
    for (int mi = 0; mi < 2; mi++)
#pragma unroll
        for (int ni = 0; ni < 8; ni++)
#pragma unroll
            for (int q = 0; q < 4; q++) c[mi][ni][q] = 0.f;

    // Loader: X tile = 128 rows x 8 float4-granules = 1024 granules; thread
    // handles gid = tid + 256*j, j=0..3 -> row = gid>>3 (0..127),
    // col = (gid&7)*4 (0..28). Same mapping for W.
#define LOAD_TILE(buf, kt)                                                     \
    do {                                                                       \
        float* xd_ = smem + (buf) * STG_FLOATS;                                \
        float* wd_ = xd_ + X_STG;                                              \
        _Pragma("unroll")                                                      \
        for (int j_ = 0; j_ < 4; j_++) {                                       \
            int gid_ = tid + 256 * j_;                                         \
            int row_ = gid_ >> 3;                                              \
            int col_ = (gid_ & 7) * 4;                                         \
            cp_async16(&xd_[row_ * XS_STRIDE + col_],                          \
                       X + (size_t)(m0g + row_) * K_TOT + (kt) + col_);        \
            cp_async16(&wd_[row_ * XS_STRIDE + col_],                          \
                       W + (size_t)(n0 + row_) * K_TOT + (kt) + col_);         \
        }                                                                      \
    } while (0)

    // prologue: tiles 0,1,2 -> buffers 0,1,2
#pragma unroll
    for (int t = 0; t < NSTG - 1; t++) {
        LOAD_TILE(t, t * BK);
        cp_commit();
    }

    for (int t = 0; t < NT; t++) {
        cp_wait<NSTG - 2>();   // tile t landed (this thread's groups)
        __syncthreads();       // everyone's tile t landed; compute t-1 done

        if (t + NSTG - 1 < NT)
            LOAD_TILE((t + NSTG - 1) & (NSTG - 1), (t + NSTG - 1) * BK);
        cp_commit();           // one group per iteration (possibly empty)

        const float* xb = smem + (t & (NSTG - 1)) * STG_FLOATS;
        const float* wb = xb + X_STG;

#pragma unroll
        for (int kk = 0; kk < BK / 8; kk++) {
            const int k = kk * 8;
            unsigned af[2][4], bf[8][2];
#pragma unroll
            for (int mi = 0; mi < 2; mi++) {
                // rows mbase+mi*16+g and +8: max 96+16+7+8 = 127 < 128 ✓
                const float* xr = xb + (mbase + mi * 16 + g) * XS_STRIDE + k + tig;
                af[mi][0] = __float_as_uint(xr[0]);
                af[mi][1] = __float_as_uint(xr[8 * XS_STRIDE]);
                af[mi][2] = __float_as_uint(xr[4]);
                af[mi][3] = __float_as_uint(xr[8 * XS_STRIDE + 4]);
            }
#pragma unroll
            for (int ni = 0; ni < 8; ni++) {
                // rows nbase+ni*8+g: max 64+56+7 = 127 < 128 ✓
                const float* wrp = wb + (nbase + ni * 8 + g) * XS_STRIDE + k + tig;
                bf[ni][0] = __float_as_uint(wrp[0]);
                bf[ni][1] = __float_as_uint(wrp[4]);
            }
#pragma unroll
            for (int mi = 0; mi < 2; mi++)
#pragma unroll
                for (int ni = 0; ni < 8; ni++)
                    mma_tf32(c[mi][ni], af[mi], bf[ni]);
        }
    }
    __syncthreads();

    // epilogue: exact fp32 rank-16 LoRA correction + direct stores
#pragma unroll
    for (int mi = 0; mi < 2; mi++) {
        const int m0r = mbase + mi * 16 + g;      // <= 119
        const int m1r = m0r + 8;                  // <= 127
#pragma unroll
        for (int ni = 0; ni < 8; ni++) {
            const int nl = nbase + ni * 8 + 2 * tig;   // <= 126
            float d00 = 0.f, d01 = 0.f, d10 = 0.f, d11 = 0.f;
#pragma unroll
            for (int r = 0; r < R_LORA; r++) {
                float t0 = Ts[m0r * TS_STRIDE + r];
                float t1 = Ts[m1r * TS_STRIDE + r];
                float a0 = As[nl * AS_STRIDE + r];
                float a1 = As[(nl + 1) * AS_STRIDE + r];
                d00 += t0 * a0;
                d01 += t0 * a1;
                d10 += t1 * a0;
                d11 += t1 * a1;
            }
            size_t o0 = (size_t)(m0g + m0r) * N_TOT + n0 + nl;   // row <= 255
            size_t o1 = (size_t)(m0g + m1r) * N_TOT + n0 + nl;
            float2 v0 = make_float2(c[mi][ni][0] + d00, c[mi][ni][1] + d01);
            float2 v1 = make_float2(c[mi][ni][2] + d10, c[mi][ni][3] + d11);
            *reinterpret_cast<float2*>(Out + o0) = v0;
            *reinterpret_cast<float2*>(Out + o1) = v1;
        }
    }
#undef LOAD_TILE
}

// ---------------------------------------------------------------------------
extern "C" void kernel_launch(void* const* d_in, const int* in_sizes, int n_in,
                              void* d_out, int out_size)
{
    const float* x  = (const float*)d_in[0];  // [4,64,8192]
    const float* W  = (const float*)d_in[1];  // [8192,8192]
    const float* A  = (const float*)d_in[2];  // [8192,16]
    const float* Bm = (const float*)d_in[3];  // [16,8192]
    float* out = (float*)d_out;               // [4,64,8192]

    cudaFuncSetAttribute(lora_gemm_kernel,
                         cudaFuncAttributeMaxDynamicSharedMemorySize, SMEM_BYTES);

    lora_xbt_kernel<<<64, 256>>>(x, Bm);
    lora_gemm_kernel<<<128, 256, SMEM_BYTES>>>(x, W, A, out);
}